// round 4
// baseline (speedup 1.0000x reference)
#include <cuda_runtime.h>
#include <cuda_bf16.h>
#include <math.h>

// Problem constants
#define BB   32
#define TT   2048
#define EE   256        // K
#define HH   256
#define LBL  20

// GEMM tiling
#define KC      32      // K chunk staged in smem
#define XSTR    36      // padded stride (conflict-free)
#define WSTR    36
#define NT_BLK  16      // T tiles of 128 rows
#define CG_BLK  8       // 2 dirs * 4 h-groups of 64

// ---------------- scratch (no allocations allowed) ----------------
__device__ float g_Wpack[1536 * 256];          // tf32-rounded, blocked layout
__device__ float g_bias[1536];                 // b_ih + b_hh, same layout
__device__ float g_psum[NT_BLK * BB * 512];    // per-tile partial sums
__device__ float g_pmax[NT_BLK * BB * 512];    // per-tile partial maxes
__device__ float g_doc[BB * 1024];             // [avg(512), max(512)]

__device__ __forceinline__ float sigmoidf_(float x) { return 1.0f / (1.0f + expf(-x)); }

__device__ __forceinline__ unsigned f2tf32(float f) {
    unsigned u;
    asm("cvt.rna.tf32.f32 %0, %1;" : "=r"(u) : "f"(f));
    return u;
}

__device__ __forceinline__ void mma8(float& c0, float& c1, float& c2, float& c3,
                                     unsigned a0, unsigned a1, unsigned a2, unsigned a3,
                                     unsigned b0, unsigned b1) {
    asm volatile(
        "mma.sync.aligned.m16n8k8.row.col.f32.tf32.tf32.f32 "
        "{%0,%1,%2,%3}, {%4,%5,%6,%7}, {%8,%9}, {%0,%1,%2,%3};"
        : "+f"(c0), "+f"(c1), "+f"(c2), "+f"(c3)
        : "r"(a0), "r"(a1), "r"(a2), "r"(a3), "r"(b0), "r"(b1));
}

// ---------------- pack W (skip dead 'f' gate) + fuse biases ----------------
// Layout: c = ((dir*4 + hgrp)*3 + gate)*64 + j   (gate: 0=i, 1=g, 2=o), K contiguous
__global__ void pack_w_kernel(const float* __restrict__ Wf, const float* __restrict__ bif,
                              const float* __restrict__ bhf,
                              const float* __restrict__ Wr, const float* __restrict__ bir,
                              const float* __restrict__ bhr) {
    int c = blockIdx.x;          // 0..1535
    int k = threadIdx.x;         // 0..255
    int cg = c / 192, within = c % 192;
    int gate = within / 64, j = within % 64;
    int dir = cg / 4, hgrp = cg % 4;
    int gsel = (gate == 0) ? 0 : (gate == 1 ? 2 : 3);   // torch gate order i,f,g,o
    int srow = gsel * 256 + hgrp * 64 + j;
    const float* W = dir ? Wr : Wf;
    g_Wpack[c * 256 + k] = __uint_as_float(f2tf32(W[srow * 256 + k]));
    if (k == 0) {
        const float* bi = dir ? bir : bif;
        const float* bh = dir ? bhr : bhf;
        g_bias[c] = bi[srow] + bh[srow];
    }
}

// ---------------- fused GEMM + activation + masked pooling ----------------
// block: (cg, tblk, b). Computes C[128 x 192] = X_tile @ Wsub, then
// h = sigmoid(o)*tanh(sigmoid(i)*tanh(g)) for 128 t-rows x 64 h-cols,
// and masked partial sum/max over the 128 rows.
__global__ void __launch_bounds__(256)
gemm_fused_kernel(const float* __restrict__ X, const int* __restrict__ lengths) {
    __shared__ float smem[128 * XSTR + 192 * WSTR];   // 46,080 B, also reused by epilogue
    float* Xs = smem;                 // [128][36]
    float* Ws = smem + 128 * XSTR;    // [192][36]
    float* Se = smem;                 // epilogue: [32][196]
    float* Spart = smem + 32 * 196;   // [256]
    float* Mpart = Spart + 256;       // [256]

    const int cg = blockIdx.x, tblk = blockIdx.y, b = blockIdx.z;
    const int tid = threadIdx.x, lane = tid & 31, warp = tid >> 5;
    const int wm = warp & 3, wn = warp >> 2;       // 4 M-warps x 2 N-warps
    const int m0 = b * TT + tblk * 128;
    const float* Wp = g_Wpack + (size_t)cg * 192 * 256;

    float acc[2][12][4];
#pragma unroll
    for (int mt = 0; mt < 2; mt++)
#pragma unroll
        for (int nt = 0; nt < 12; nt++)
#pragma unroll
            for (int q = 0; q < 4; q++) acc[mt][nt][q] = 0.0f;

    for (int kc = 0; kc < EE / KC; kc++) {
        const int kb = kc * KC;
        // stage X tile 128x32 (convert to tf32)
#pragma unroll
        for (int it = 0; it < 4; it++) {
            int idx = tid + it * 256;
            int i = idx >> 3, k4 = idx & 7;
            float4 v = *(const float4*)(X + (size_t)(m0 + i) * EE + kb + k4 * 4);
            v.x = __uint_as_float(f2tf32(v.x));
            v.y = __uint_as_float(f2tf32(v.y));
            v.z = __uint_as_float(f2tf32(v.z));
            v.w = __uint_as_float(f2tf32(v.w));
            *(float4*)(Xs + i * XSTR + k4 * 4) = v;
        }
        // stage W tile 192x32 (already tf32)
#pragma unroll
        for (int it = 0; it < 6; it++) {
            int idx = tid + it * 256;
            int n = idx >> 3, k4 = idx & 7;
            float4 v = *(const float4*)(Wp + (size_t)n * 256 + kb + k4 * 4);
            *(float4*)(Ws + n * WSTR + k4 * 4) = v;
        }
        __syncthreads();

#pragma unroll
        for (int k8 = 0; k8 < KC / 8; k8++) {
            const int ck = k8 * 8 + (lane & 3);
            unsigned a[2][4];
#pragma unroll
            for (int mt = 0; mt < 2; mt++) {
                int r0 = wm * 32 + mt * 16 + (lane >> 2);
                a[mt][0] = __float_as_uint(Xs[r0 * XSTR + ck]);
                a[mt][1] = __float_as_uint(Xs[(r0 + 8) * XSTR + ck]);
                a[mt][2] = __float_as_uint(Xs[r0 * XSTR + ck + 4]);
                a[mt][3] = __float_as_uint(Xs[(r0 + 8) * XSTR + ck + 4]);
            }
#pragma unroll
            for (int nt = 0; nt < 12; nt++) {
                int n = wn * 96 + nt * 8 + (lane >> 2);
                unsigned b0 = __float_as_uint(Ws[n * WSTR + ck]);
                unsigned b1 = __float_as_uint(Ws[n * WSTR + ck + 4]);
                mma8(acc[0][nt][0], acc[0][nt][1], acc[0][nt][2], acc[0][nt][3],
                     a[0][0], a[0][1], a[0][2], a[0][3], b0, b1);
                mma8(acc[1][nt][0], acc[1][nt][1], acc[1][nt][2], acc[1][nt][3],
                     a[1][0], a[1][1], a[1][2], a[1][3], b0, b1);
            }
        }
        __syncthreads();
    }

    // ------------- epilogue: activation + masked pooling, 32 rows at a time -------------
    int len = lengths[b];
    len = min(max(len, 1), TT);
    const int t0 = tblk * 128;
    const int j = tid & 63, sub = tid >> 6;     // 64 h-cols, 4 row-groups
    const float bi = g_bias[cg * 192 + j];
    const float bg = g_bias[cg * 192 + 64 + j];
    const float bo = g_bias[cg * 192 + 128 + j];
    float psum = 0.0f, pmax = -1e30f;

    for (int q = 0; q < 4; q++) {               // 32-row chunks of the 128-row tile
        if (wm == q) {                          // owning warps dump their C rows
#pragma unroll
            for (int mt = 0; mt < 2; mt++) {
                int rr = mt * 16 + (lane >> 2);
                int cb = wn * 96 + (lane & 3) * 2;
#pragma unroll
                for (int nt = 0; nt < 12; nt++) {
                    Se[rr * 196 + cb + nt * 8]           = acc[mt][nt][0];
                    Se[rr * 196 + cb + nt * 8 + 1]       = acc[mt][nt][1];
                    Se[(rr + 8) * 196 + cb + nt * 8]     = acc[mt][nt][2];
                    Se[(rr + 8) * 196 + cb + nt * 8 + 1] = acc[mt][nt][3];
                }
            }
        }
        __syncthreads();
#pragma unroll
        for (int rr = 0; rr < 8; rr++) {
            int rloc = sub * 8 + rr;
            float gi = Se[rloc * 196 + j] + bi;
            float gg = Se[rloc * 196 + 64 + j] + bg;
            float go = Se[rloc * 196 + 128 + j] + bo;
            float cc = sigmoidf_(gi) * tanhf(gg);
            float h  = sigmoidf_(go) * tanhf(cc);
            int t = t0 + q * 32 + rloc;
            if (t < len) { psum += h; pmax = fmaxf(pmax, h); }
        }
        __syncthreads();
    }

    Spart[tid] = psum;
    Mpart[tid] = pmax;
    __syncthreads();
    if (tid < 64) {
        float s = Spart[tid] + Spart[64 + tid] + Spart[128 + tid] + Spart[192 + tid];
        float m = fmaxf(fmaxf(Mpart[tid], Mpart[64 + tid]),
                        fmaxf(Mpart[128 + tid], Mpart[192 + tid]));
        int dir = cg >> 2, hgrp = cg & 3;
        int col = dir * 256 + hgrp * 64 + tid;
        g_psum[(tblk * BB + b) * 512 + col] = s;
        g_pmax[(tblk * BB + b) * 512 + col] = m;
    }
}

// ---------------- deterministic reduction over T-tiles -> doc[B,1024] ----------------
__global__ void reduce_doc_kernel(const int* __restrict__ lengths) {
    int b = blockIdx.x, col = threadIdx.x;   // 512 threads
    float s = 0.0f, m = -1e30f;
#pragma unroll
    for (int t = 0; t < NT_BLK; t++) {
        s += g_psum[(t * BB + b) * 512 + col];
        m = fmaxf(m, g_pmax[(t * BB + b) * 512 + col]);
    }
    int len = lengths[b];
    len = min(max(len, 1), TT);
    g_doc[b * 1024 + col]       = s / (float)len;
    g_doc[b * 1024 + 512 + col] = m;
}

// ---------------- MLP head: relu(doc) @ W1^T + b1 -> @ W2^T + b2 ----------------
__global__ void mlp_kernel(const float* __restrict__ W1, const float* __restrict__ b1,
                           const float* __restrict__ W2, const float* __restrict__ b2,
                           float* __restrict__ out) {
    __shared__ float sdoc[1024];
    __shared__ float sd1[256];
    int b = blockIdx.x, tid = threadIdx.x, lane = tid & 31, warp = tid >> 5;
    for (int k = tid; k < 1024; k += 256) sdoc[k] = fmaxf(g_doc[b * 1024 + k], 0.0f);
    __syncthreads();
    // layer 1: warp-per-output, coalesced W1 reads, shuffle reduce
    for (int jj = 0; jj < 32; jj++) {
        int jo = warp * 32 + jj;
        float a = 0.0f;
#pragma unroll
        for (int kk = 0; kk < 32; kk++) {
            int k = lane + kk * 32;
            a += sdoc[k] * W1[(size_t)jo * 1024 + k];
        }
#pragma unroll
        for (int o = 16; o > 0; o >>= 1) a += __shfl_down_sync(0xffffffffu, a, o);
        if (lane == 0) sd1[jo] = a + b1[jo];
    }
    __syncthreads();
    // layer 2: tiny
    if (tid < LBL) {
        float a = b2[tid];
#pragma unroll 8
        for (int k = 0; k < 256; k++) a += sd1[k] * W2[tid * 256 + k];
        out[b * LBL + tid] = a;
    }
}

extern "C" void kernel_launch(void* const* d_in, const int* in_sizes, int n_in,
                              void* d_out, int out_size) {
    const float* X       = (const float*)d_in[0];
    const int*   lengths = (const int*)d_in[1];
    const float* W_ih_f  = (const float*)d_in[2];
    const float* b_ih_f  = (const float*)d_in[3];
    const float* b_hh_f  = (const float*)d_in[4];
    const float* W_ih_r  = (const float*)d_in[5];
    const float* b_ih_r  = (const float*)d_in[6];
    const float* b_hh_r  = (const float*)d_in[7];
    const float* W1      = (const float*)d_in[8];
    const float* b1      = (const float*)d_in[9];
    const float* W2      = (const float*)d_in[10];
    const float* b2      = (const float*)d_in[11];
    float* out = (float*)d_out;

    pack_w_kernel<<<1536, 256>>>(W_ih_f, b_ih_f, b_hh_f, W_ih_r, b_ih_r, b_hh_r);
    dim3 grid(CG_BLK, NT_BLK, BB);
    gemm_fused_kernel<<<grid, 256>>>(X, lengths);
    reduce_doc_kernel<<<BB, 512>>>(lengths);
    mlp_kernel<<<BB, 256>>>(W1, b1, W2, b2, out);
}